// round 5
// baseline (speedup 1.0000x reference)
#include <cuda_runtime.h>
#include <cuda_bf16.h>

#define B_ 4
#define T_ 2048
#define H_ 16
#define D_ 128
#define HD 2048        // H_*D_
#define S_ 16          // steps per chunk
#define NC (T_/S_)     // 128 chunks

// dynamic smem layout (float offsets)
#define FS_OFF 0        // f rows:  16 t * 160
#define KS_OFF 2560     // kg rows
#define QS_OFF 5120     // q rows
#define VG_OFF 7680     // vg cols: 16 t * 64
#define PT_OFF 8704     // partials: 16 t * (64 cols * 4 rowgroups)
#define SM_FLOATS 12800 // 51200 bytes

typedef unsigned long long u64;

__device__ __forceinline__ u64 pk2(float x, float y) {
    u64 r; asm("mov.b64 %0,{%1,%2};" : "=l"(r) : "f"(x), "f"(y)); return r;
}
__device__ __forceinline__ float2 up2(u64 a) {
    float2 r; asm("mov.b64 {%0,%1},%2;" : "=f"(r.x), "=f"(r.y) : "l"(a)); return r;
}
__device__ __forceinline__ u64 mul2(u64 a, u64 b) {
    u64 d; asm("mul.rn.f32x2 %0,%1,%2;" : "=l"(d) : "l"(a), "l"(b)); return d;
}
__device__ __forceinline__ u64 add2(u64 a, u64 b) {
    u64 d; asm("add.rn.f32x2 %0,%1,%2;" : "=l"(d) : "l"(a), "l"(b)); return d;
}
__device__ __forceinline__ u64 fma2(u64 a, u64 b, u64 c) {
    u64 d; asm("fma.rn.f32x2 %0,%1,%2,%3;" : "=l"(d) : "l"(a), "l"(b), "l"(c)); return d;
}
__device__ __forceinline__ u64 max2c(u64 a, float c) {
    float2 t = up2(a);
    t.x = fmaxf(t.x, c); t.y = fmaxf(t.y, c);   // 2x FMNMX on alu pipe
    return pk2(t.x, t.y);
}

// Row tile layout per t: 8 blocks of (16 floats + 4 pad) = 160 floats.
// float4 block a (rows 4a..4a+3): off = (a>>2)*20 + (a&3)*4 -> conflict-free LDS.128.
__global__ __launch_bounds__(256, 1) void delta_kernel(
    const float* __restrict__ q, const float* __restrict__ k,
    const float* __restrict__ v, const float* __restrict__ f,
    const float* __restrict__ g, float* __restrict__ out)
{
    extern __shared__ float smp[];

    const int tid  = threadIdx.x;
    const int w    = tid >> 5, lane = tid & 31;
    const int c    = lane & 7;           // 8 col-lanes
    const int r    = lane >> 3;          // 4 rowgroups of 32 rows
    const int colbase = blockIdx.x * 64;
    const long base0  = (long)blockIdx.z * T_ * HD + (long)blockIdx.y * D_;

    const int cj = w * 8 + c;            // local column [0,64)
    const int dj = colbase + cj;         // global d index of my column
    const int rl = r * 40;               // row tile read base (32 rows)
    const int fcidx = (dj >> 4) * 20 + (dj & 15);
    const int ptidx = PT_OFF + cj * 4 + r;

    // staging roles: each thread stages 8 rows (2 float4) and 4 cols per t
    const int  t_s = tid >> 4, rb = tid & 15;
    const long growb = base0 + (long)t_s * HD + rb * 8;
    const long gcolb = base0 + (long)t_s * HD + colbase + rb * 4;
    const int  wroff = t_s * 160 + (rb >> 1) * 20 + (rb & 1) * 8;  // + second f4 at +4
    const int  vgoff = VG_OFF + t_s * 64 + rb * 4;

    // prefetch chunk 0
    float4 pq0 = *(const float4*)(q + growb),     pq1 = *(const float4*)(q + growb + 4);
    float4 pk0 = *(const float4*)(k + growb),     pk1 = *(const float4*)(k + growb + 4);
    float4 pg0 = *(const float4*)(g + growb),     pg1 = *(const float4*)(g + growb + 4);
    float4 pf0 = *(const float4*)(f + growb),     pf1 = *(const float4*)(f + growb + 4);
    float4 cv  = *(const float4*)(v + gcolb),     cgv = *(const float4*)(g + gcolb);

    // state: 32 rows x 1 col = 16 packed f32x2 chains
    u64 M[16];
#pragma unroll
    for (int p = 0; p < 16; p++) M[p] = 0ull;

    const int OFF[8] = {0, 4, 8, 12, 20, 24, 28, 32};

    for (int ch = 0; ch < NC; ch++) {
        // ---- reduce previous chunk's partials -> gmem (disjoint smem from tiles) ----
        if (ch > 0) {
            const long obase = base0 + (long)(ch - 1) * S_ * HD + colbase;
#pragma unroll
            for (int ii = 0; ii < 4; ii++) {
                const int idx = tid + ii * 256;
                const int s2 = idx >> 6, col = idx & 63;
                const float4 a = *(const float4*)(smp + PT_OFF + s2 * 256 + col * 4);
                out[obase + (long)s2 * HD + col] = (a.x + a.y) + (a.z + a.w);
            }
        }
        // ---- stage prefetched regs -> smem tiles ----
        {
            float4 kg0, kg1;
            kg0.x = pk0.x * pg0.x; kg0.y = pk0.y * pg0.y;
            kg0.z = pk0.z * pg0.z; kg0.w = pk0.w * pg0.w;
            kg1.x = pk1.x * pg1.x; kg1.y = pk1.y * pg1.y;
            kg1.z = pk1.z * pg1.z; kg1.w = pk1.w * pg1.w;
            *(float4*)(smp + FS_OFF + wroff)     = pf0;
            *(float4*)(smp + FS_OFF + wroff + 4) = pf1;
            *(float4*)(smp + KS_OFF + wroff)     = kg0;
            *(float4*)(smp + KS_OFF + wroff + 4) = kg1;
            *(float4*)(smp + QS_OFF + wroff)     = pq0;
            *(float4*)(smp + QS_OFF + wroff + 4) = pq1;
            float4 vg;
            vg.x = cv.x * cgv.x; vg.y = cv.y * cgv.y;
            vg.z = cv.z * cgv.z; vg.w = cv.w * cgv.w;
            *(float4*)(smp + vgoff) = vg;
        }
        __syncthreads();
        // ---- prefetch next chunk (lands during compute) ----
        if (ch + 1 < NC) {
            const long off = (long)(ch + 1) * S_ * HD;
            pq0 = *(const float4*)(q + growb + off); pq1 = *(const float4*)(q + growb + off + 4);
            pk0 = *(const float4*)(k + growb + off); pk1 = *(const float4*)(k + growb + off + 4);
            pg0 = *(const float4*)(g + growb + off); pg1 = *(const float4*)(g + growb + off + 4);
            pf0 = *(const float4*)(f + growb + off); pf1 = *(const float4*)(f + growb + off + 4);
            cv  = *(const float4*)(v + gcolb + off); cgv = *(const float4*)(g + gcolb + off);
        }
        // ---- compute 16 steps ----
#pragma unroll
        for (int s = 0; s < S_; s++) {
            const float* fb = smp + FS_OFF + s * 160 + rl;
            const float* kb = smp + KS_OFF + s * 160 + rl;
            const float* qb = smp + QS_OFF + s * 160 + rl;
            const float fc  = smp[FS_OFF + s * 160 + fcidx];
            const float vgc = smp[VG_OFF + s * 64 + cj];
            const u64 fj = pk2(fc, fc);
            const u64 vj = pk2(vgc, vgc);
            u64 oa0 = 0ull, oa1 = 0ull, oa2 = 0ull, oa3 = 0ull;
#pragma unroll
            for (int i = 0; i < 8; i++) {
                const int o = OFF[i];
                ulonglong2 f2 = *(const ulonglong2*)(fb + o);
                ulonglong2 k2 = *(const ulonglong2*)(kb + o);
                ulonglong2 q2 = *(const ulonglong2*)(qb + o);
                u64 fo;
                fo = max2c(mul2(f2.x, fj), 0.8f);
                M[i * 2]     = fma2(M[i * 2], fo, mul2(k2.x, vj));
                fo = max2c(mul2(f2.y, fj), 0.8f);
                M[i * 2 + 1] = fma2(M[i * 2 + 1], fo, mul2(k2.y, vj));
                if (i & 1) {
                    oa2 = fma2(q2.x, M[i * 2],     oa2);
                    oa3 = fma2(q2.y, M[i * 2 + 1], oa3);
                } else {
                    oa0 = fma2(q2.x, M[i * 2],     oa0);
                    oa1 = fma2(q2.y, M[i * 2 + 1], oa1);
                }
            }
            const float2 tt = up2(add2(add2(oa0, oa1), add2(oa2, oa3)));
            smp[ptidx + s * 256] = tt.x + tt.y;   // fire-and-forget STS.32, 1 wf
        }
        __syncthreads();
    }
    // ---- final chunk's reduction ----
    {
        const long obase = base0 + (long)(NC - 1) * S_ * HD + colbase;
#pragma unroll
        for (int ii = 0; ii < 4; ii++) {
            const int idx = tid + ii * 256;
            const int s2 = idx >> 6, col = idx & 63;
            const float4 a = *(const float4*)(smp + PT_OFF + s2 * 256 + col * 4);
            out[obase + (long)s2 * HD + col] = (a.x + a.y) + (a.z + a.w);
        }
    }
}

extern "C" void kernel_launch(void* const* d_in, const int* in_sizes, int n_in,
                              void* d_out, int out_size) {
    const float* q = (const float*)d_in[0];
    const float* k = (const float*)d_in[1];
    const float* v = (const float*)d_in[2];
    const float* f = (const float*)d_in[3];
    const float* g = (const float*)d_in[4];
    cudaFuncSetAttribute(delta_kernel,
                         cudaFuncAttributeMaxDynamicSharedMemorySize,
                         SM_FLOATS * sizeof(float));
    dim3 grid(2, H_, B_);
    delta_kernel<<<grid, 256, SM_FLOATS * sizeof(float)>>>(q, k, v, f, g, (float*)d_out);
}